// round 6
// baseline (speedup 1.0000x reference)
#include <cuda_runtime.h>
#include <math.h>

#define BB 128
#define TT 512
#define DD 128
#define HH 384
#define GG 1542
#define GPAD 1664       // 13 tiles of 128 for xk kernel
#define HSS 64
#define CK 10
#define GT 25           // phase1 g-tiles of 64 (25*64=1600 >= 1542)
#define NBLK (GT * 4)   // 100 blocks
#define KH 384          // recurrent K (h only)

__device__ float g_h[(size_t)TT * BB * HH];
__device__ float g_c[BB * HH];
__device__ float g_xout[BB * GG];
__device__ float g_dist[TT * BB];
__device__ float g_theme[(size_t)TT * BB * HH];
__device__ float g_wct[CK * HH * HH];
__device__ float g_xk[(size_t)TT * BB * GPAD];   // x@Wk + bias, padded (zero-init)
__device__ unsigned g_cnt2[4];
__device__ volatile unsigned g_gen2[4];

typedef unsigned long long u64;
__device__ __forceinline__ u64 pk2(float a, float b) {
    u64 r; asm("mov.b64 %0,{%1,%2};" : "=l"(r) : "f"(a), "f"(b)); return r;
}
__device__ __forceinline__ void fma2(u64 &d, u64 a, u64 b) {
    asm("fma.rn.f32x2 %0,%1,%2,%0;" : "+l"(d) : "l"(a), "l"(b));
}
__device__ __forceinline__ float2 up2(u64 v) {
    float2 r; asm("mov.b64 {%0,%1},%2;" : "=f"(r.x), "=f"(r.y) : "l"(v)); return r;
}
__device__ __forceinline__ float sgm(float x) { return 1.f / (1.f + expf(-x)); }

__device__ __forceinline__ void group_bar(int grp) {
    __syncthreads();
    if (threadIdx.x == 0) {
        unsigned old = g_gen2[grp];
        __threadfence();
        if (atomicAdd(&g_cnt2[grp], 1u) == GT - 1) {
            g_cnt2[grp] = 0;
            __threadfence();
            g_gen2[grp] = old + 1;
        } else {
            while (g_gen2[grp] == old) { }
            __threadfence();
        }
    }
    __syncthreads();
}

__device__ __forceinline__ void calc_dis(int t, int b, float *dis) {
    float cs = 0.f, c[CK];
    #pragma unroll
    for (int k = 0; k < CK; k++) {
        int s = t - (CK - 1) + k;
        cs += (s >= 0) ? g_dist[s * BB + b] : 0.f;
        c[k] = cs;
    }
    float mx = c[0];
    #pragma unroll
    for (int k = 1; k < CK; k++) mx = fmaxf(mx, c[k]);
    float sum = 0.f;
    #pragma unroll
    for (int k = 0; k < CK; k++) { c[k] = expf(c[k] - mx); sum += c[k]; }
    float is = 1.f / sum;
    #pragma unroll
    for (int k = 0; k < CK; k++) dis[k] = c[k] * is;
}

// Wc[o][i][k] -> g_wct[k][i][o]
__global__ void wct_kernel(const float * __restrict__ Wc) {
    int e = blockIdx.x * 256 + threadIdx.x;
    if (e < CK * HH * HH) {
        int o = e % HH, i = (e / HH) % HH, k = e / (HH * HH);
        g_wct[e] = Wc[((size_t)o * HH + i) * CK + k];
    }
}

// ---------- XK precompute: g_xk[t][b][g] = x[b,t]@Wk + (bk+br+Wk[D]+Wr[H]) ----------
// grid (512: b*4+tt, 13 g-tiles of 128), tile 128t x 128g, K=128, micro 8t x 8g.
#define XK_FFMA(COMP)                                                       \
    {                                                                       \
        ulonglong2 b0v = *(const ulonglong2 *)&Bs[kk][tx * 4];              \
        ulonglong2 b1v = *(const ulonglong2 *)&Bs[kk][tx * 4 + 64];         \
        _Pragma("unroll")                                                   \
        for (int rr = 0; rr < 8; rr++) {                                    \
            float av = a4[rr].COMP;                                         \
            u64 aa = pk2(av, av);                                           \
            fma2(acc[rr][0], aa, b0v.x); fma2(acc[rr][1], aa, b0v.y);       \
            fma2(acc[rr][2], aa, b1v.x); fma2(acc[rr][3], aa, b1v.y);       \
        }                                                                   \
        kk++;                                                               \
    }

__global__ __launch_bounds__(256) void xk_kernel(
    const float * __restrict__ x, const float * __restrict__ Wk,
    const float * __restrict__ bk, const float * __restrict__ Wr,
    const float * __restrict__ br)
{
    int b = blockIdx.x >> 2, t0 = (blockIdx.x & 3) * 128;
    int g0 = blockIdx.y * 128;
    int tid = threadIdx.x, tx = tid & 15, ty = tid >> 4;
    __shared__ __align__(16) float As[128][20];
    __shared__ __align__(16) float Bs[16][128];

    u64 acc[8][4];
    #pragma unroll
    for (int a = 0; a < 8; a++)
        #pragma unroll
        for (int c = 0; c < 4; c++) acc[a][c] = 0ull;

    for (int ch = 0; ch < 8; ch++) {
        int k0 = ch * 16;
        __syncthreads();
        #pragma unroll
        for (int l = 0; l < 8; l++) {
            int e = tid + l * 256;
            As[e >> 4][e & 15] = x[((size_t)b * TT + t0 + (e >> 4)) * DD + k0 + (e & 15)];
            int g = g0 + (e & 127);
            Bs[e >> 7][e & 127] = (g < GG) ? Wk[(size_t)(k0 + (e >> 7)) * GG + g] : 0.f;
        }
        __syncthreads();
        #pragma unroll
        for (int kq = 0; kq < 4; kq++) {
            float4 a4[8];
            #pragma unroll
            for (int rr = 0; rr < 8; rr++)
                a4[rr] = *(const float4 *)&As[ty * 8 + rr][kq * 4];
            int kk = kq * 4;
            XK_FFMA(x) XK_FFMA(y) XK_FFMA(z) XK_FFMA(w)
        }
    }
    #pragma unroll
    for (int rr = 0; rr < 8; rr++) {
        int t = t0 + ty * 8 + rr;
        #pragma unroll
        for (int c = 0; c < 4; c++) {
            float2 v = up2(acc[rr][c]);
            #pragma unroll
            for (int l = 0; l < 2; l++) {
                int g = g0 + (c >> 1) * 64 + tx * 4 + (c & 1) * 2 + l;
                if (g < GG) {
                    float bias = bk[g] + br[g] + Wk[(size_t)DD * GG + g] + Wr[(size_t)HH * GG + g];
                    g_xk[((size_t)t * BB + b) * GPAD + g] = (l ? v.y : v.x) + bias;
                }
            }
        }
    }
}

// ---------- Persistent phase-1: recurrent GEMM (K=384) + state update ----------
// 100 blocks in 4 groups of 25 (per b-tile). 256 thr: 4-way split-K, micro 4b x 8g.
__global__ __launch_bounds__(256, 1) void phase1_kernel()
{
    extern __shared__ float sm[];
    float *Bs = sm;                  // [384][64]
    float *As = sm + KH * 64;        // [384][36]  (also aliased as split-K red)

    int tid = threadIdx.x, blk = blockIdx.x;
    int gt = blk % GT, bt = blk / GT;
    int g0 = gt * 64, b0 = bt * 32;

    // weights come preprocessed through... no: load Wr slice once into SMEM via g ref
    // (Wr passed via const global pointer stored before launch is not possible ->
    //  use __grid_constant__-free path: read from g_wr? Simplest: reuse g_xout? No.)
    // -> Wr is passed through a device pointer baked in by a copy kernel is overkill:
    //    we read Wr directly from param-less path is impossible, so Wr slice is staged
    //    by reading from g_wr_ptr set below.
    // (see host: phase1 gets Wr via kernel arg)
    // placeholder; real body in phase1_body
    (void)As; (void)Bs; (void)g0; (void)b0; (void)gt; (void)bt; (void)tid;
}

__global__ __launch_bounds__(256, 1) void phase1_main(const float * __restrict__ Wr)
{
    extern __shared__ float sm[];
    float *Bs = sm;                  // [384][64]
    float *As = sm + KH * 64;        // [384][36]

    int tid = threadIdx.x, blk = blockIdx.x;
    int gt = blk % GT, bt = blk / GT;
    int g0 = gt * 64, b0 = bt * 32;

    // one-time: Wr slice (zero-padded g) into SMEM
    for (int j = 0; j < (KH * 64) / 256; j++) {
        int e = tid + j * 256;
        int gg = e & 63, k = e >> 6, g = g0 + gg;
        Bs[e] = (g < GG) ? Wr[(size_t)k * GG + g] : 0.f;
    }
    // zero c for this group's b-tile (same partition as update loop)
    for (int e = gt * 256 + tid; e < 32 * HH; e += GT * 256) g_c[b0 * HH + e] = 0.f;
    __syncthreads();

    int kc = tid >> 6, r = tid & 63;
    int tx = r & 7, ty = r >> 3;          // tx: g-quad pair, ty: 4-b group
    int sb = tid >> 3, sj = tid & 7;      // staging

    for (int t = 0; t < TT; t++) {
        // stage h_{t-1}[b0..b0+31][0..383] into As[k][b] (pad 36)
        #pragma unroll
        for (int j = 0; j < 12; j++) {
            int k4 = (sj + j * 8) * 4;
            float4 v;
            if (t > 0) v = *(const float4 *)&g_h[((size_t)(t - 1) * BB + b0 + sb) * HH + k4];
            else { v.x = v.y = v.z = v.w = 0.f; }
            As[(k4 + 0) * 36 + sb] = v.x;
            As[(k4 + 1) * 36 + sb] = v.y;
            As[(k4 + 2) * 36 + sb] = v.z;
            As[(k4 + 3) * 36 + sb] = v.w;
        }
        __syncthreads();

        u64 acc[4][4];
        #pragma unroll
        for (int a = 0; a < 4; a++)
            #pragma unroll
            for (int c = 0; c < 4; c++) acc[a][c] = 0ull;

        int kbeg = kc * (KH / 4);
        #pragma unroll 6
        for (int kk = kbeg; kk < kbeg + KH / 4; kk++) {
            float4 av = *(const float4 *)&As[kk * 36 + ty * 4];
            ulonglong2 bv0 = *(const ulonglong2 *)&Bs[kk * 64 + tx * 4];
            ulonglong2 bv1 = *(const ulonglong2 *)&Bs[kk * 64 + tx * 4 + 32];
            u64 aa;
            aa = pk2(av.x, av.x);
            fma2(acc[0][0], aa, bv0.x); fma2(acc[0][1], aa, bv0.y);
            fma2(acc[0][2], aa, bv1.x); fma2(acc[0][3], aa, bv1.y);
            aa = pk2(av.y, av.y);
            fma2(acc[1][0], aa, bv0.x); fma2(acc[1][1], aa, bv0.y);
            fma2(acc[1][2], aa, bv1.x); fma2(acc[1][3], aa, bv1.y);
            aa = pk2(av.z, av.z);
            fma2(acc[2][0], aa, bv0.x); fma2(acc[2][1], aa, bv0.y);
            fma2(acc[2][2], aa, bv1.x); fma2(acc[2][3], aa, bv1.y);
            aa = pk2(av.w, av.w);
            fma2(acc[3][0], aa, bv0.x); fma2(acc[3][1], aa, bv0.y);
            fma2(acc[3][2], aa, bv1.x); fma2(acc[3][3], aa, bv1.y);
        }
        __syncthreads();   // As now reusable as reduction buffer

        u64 *red = (u64 *)As;
        if (kc) {
            #pragma unroll
            for (int a = 0; a < 4; a++)
                #pragma unroll
                for (int c = 0; c < 4; c++)
                    red[((size_t)(kc - 1) * 64 + r) * 16 + a * 4 + c] = acc[a][c];
        }
        __syncthreads();
        if (!kc) {
            #pragma unroll
            for (int a = 0; a < 4; a++) {
                int b = b0 + ty * 4 + a;
                #pragma unroll
                for (int c = 0; c < 4; c++) {
                    float2 s = up2(acc[a][c]);
                    #pragma unroll
                    for (int q = 0; q < 3; q++) {
                        float2 o = up2(red[((size_t)q * 64 + r) * 16 + a * 4 + c]);
                        s.x += o.x; s.y += o.y;
                    }
                    int gg = (c >> 1) * 32 + tx * 4 + (c & 1) * 2;
                    int g = g0 + gg;
                    float2 xk = *(const float2 *)&g_xk[((size_t)t * BB + b) * GPAD + g];
                    if (g < GG)     g_xout[(size_t)b * GG + g]     = s.x + xk.x;
                    if (g + 1 < GG) g_xout[(size_t)b * GG + g + 1] = s.y + xk.y;
                }
            }
        }
        group_bar(bt);

        // state update for this group's 32 b
        for (int el = gt * 256 + tid; el < 32 * HH; el += GT * 256) {
            int b = b0 + el / HH, i = el % HH;
            const float *xo = g_xout + (size_t)b * GG;
            float z0 = xo[0], z1 = xo[1], z2 = xo[2];
            float m = fmaxf(z0, fmaxf(z1, z2));
            float e0 = expf(z0 - m), e1 = expf(z1 - m), e2 = expf(z2 - m);
            float inv = 1.f / (e0 + e1 + e2);
            float fm0 = e0 * inv, fm1 = fm0 + e1 * inv, fm2 = fm1 + e2 * inv;
            float y0 = xo[3], y1 = xo[4], y2 = xo[5];
            float mi = fmaxf(y0, fmaxf(y1, y2));
            float q0 = expf(y0 - mi), q1 = expf(y1 - mi), q2 = expf(y2 - mi);
            float iv = 1.f / (q0 + q1 + q2);
            float im2 = q2 * iv, im1 = im2 + q1 * iv, im0 = im1 + q0 * iv;
            int l = i >> 7;
            float fm = (l == 0) ? fm0 : (l == 1 ? fm1 : fm2);
            float im = (l == 0) ? im0 : (l == 1 ? im1 : im2);
            float fg = sgm(xo[6 + i]);
            float ig = sgm(xo[6 + HH + i]);
            float og = sgm(xo[6 + 2 * HH + i]);
            float ci = tanhf(xo[6 + 3 * HH + i]);
            float ov = fm * im;
            int e = b * HH + i;
            float cn = g_c[e] * (ov * fg + fm - ov) + ci * (ov * ig + im - ov);
            g_c[e] = cn;
            g_h[(size_t)t * BB * HH + e] = og * tanhf(cn);
            if (i == 0) g_dist[t * BB + b] = 1.f - (fm0 + fm1 + fm2) * (1.f / 3.f);
        }
        group_bar(bt);
    }
}

// ---------- theme ----------
__global__ __launch_bounds__(256) void theme_kernel(
    const float * __restrict__ Ws, const float * __restrict__ bs,
    const float * __restrict__ Wrs, const float * __restrict__ brs)
{
    int t = blockIdx.x, b0 = blockIdx.y * 8, tid = threadIdx.x;
    __shared__ float dis_s[8][CK], wm[8][HH], s1[8][HSS];
    if (tid < 8) calc_dis(t, b0 + tid, dis_s[tid]);
    __syncthreads();
    #pragma unroll
    for (int j = 0; j < 12; j++) {
        int e = tid + j * 256, b = e / HH, i = e % HH;
        float a = 0.f;
        #pragma unroll
        for (int k = 0; k < CK; k++) {
            int s = t - (CK - 1) + k;
            if (s >= 0) a += dis_s[b][k] * g_h[((size_t)s * BB + b0 + b) * HH + i];
        }
        wm[b][i] = a * (1.f / CK);
    }
    __syncthreads();
    #pragma unroll
    for (int j = 0; j < 2; j++) {
        int e = tid + j * 256, b = e / HSS, hs = e % HSS;
        float a = 0.f;
        for (int i = 0; i < HH; i++) a += wm[b][i] * Ws[i * HSS + hs];
        s1[b][hs] = fmaxf(a + bs[hs], 0.f);
    }
    __syncthreads();
    #pragma unroll
    for (int j = 0; j < 12; j++) {
        int e = tid + j * 256, b = e / HH, o = e % HH;
        float a = 0.f;
        #pragma unroll
        for (int hs = 0; hs < HSS; hs++) a += s1[b][hs] * Wrs[hs * HH + o];
        g_theme[((size_t)t * BB + b0 + b) * HH + o] = sgm(a + brs[o]);
    }
}

// ---------- conv + fused epilogue ----------
#define CONV_FFMA(COMP)                                                     \
    {                                                                       \
        ulonglong2 b0v = *(const ulonglong2 *)&Bs[kk][tx * 4];              \
        ulonglong2 b1v = *(const ulonglong2 *)&Bs[kk][tx * 4 + 64];         \
        _Pragma("unroll")                                                   \
        for (int rr = 0; rr < 8; rr++) {                                    \
            float av = a4[rr].COMP;                                         \
            u64 aa = pk2(av, av);                                           \
            fma2(acc[rr][0], aa, b0v.x); fma2(acc[rr][1], aa, b0v.y);       \
            fma2(acc[rr][2], aa, b1v.x); fma2(acc[rr][3], aa, b1v.y);       \
        }                                                                   \
        kk++;                                                               \
    }

__global__ __launch_bounds__(256) void conv_kernel(const float * __restrict__ bc,
                                                   float * __restrict__ out)
{
    int t = blockIdx.x, o0 = blockIdx.y * 128, tid = threadIdx.x;
    int tx = tid & 15, ty = tid >> 4;
    __shared__ float dis_s[BB][CK];
    __shared__ __align__(16) float As[BB][20];
    __shared__ __align__(16) float Bs[16][128];
    if (tid < BB) calc_dis(t, tid, dis_s[tid]);
    __syncthreads();

    u64 acc[8][4];
    #pragma unroll
    for (int a = 0; a < 8; a++)
        #pragma unroll
        for (int c = 0; c < 4; c++) acc[a][c] = 0ull;

    const int NCH = CK * (HH / 16);  // 240
    float pa[8], pb[8];
    {
        int s = t - (CK - 1);
        #pragma unroll
        for (int l = 0; l < 8; l++) {
            int e = tid + l * 256;
            pa[l] = (s >= 0) ? g_h[((size_t)s * BB + (e >> 4)) * HH + (e & 15)] : 0.f;
            pb[l] = g_wct[(size_t)(e >> 7) * HH + o0 + (e & 127)];
        }
    }
    for (int ch = 0; ch < NCH; ch++) {
        int k = ch / 24;
        __syncthreads();
        #pragma unroll
        for (int l = 0; l < 8; l++) {
            int e = tid + l * 256;
            As[e >> 4][e & 15] = pa[l] * dis_s[e >> 4][k];
            Bs[e >> 7][e & 127] = pb[l];
        }
        __syncthreads();
        if (ch + 1 < NCH) {
            int k2 = (ch + 1) / 24, i0 = ((ch + 1) % 24) * 16, s = t - (CK - 1) + k2;
            #pragma unroll
            for (int l = 0; l < 8; l++) {
                int e = tid + l * 256;
                pa[l] = (s >= 0) ? g_h[((size_t)s * BB + (e >> 4)) * HH + i0 + (e & 15)] : 0.f;
                pb[l] = g_wct[((size_t)k2 * HH + i0 + (e >> 7)) * HH + o0 + (e & 127)];
            }
        }
        #pragma unroll
        for (int kq = 0; kq < 4; kq++) {
            float4 a4[8];
            #pragma unroll
            for (int rr = 0; rr < 8; rr++)
                a4[rr] = *(const float4 *)&As[ty * 8 + rr][kq * 4];
            int kk = kq * 4;
            CONV_FFMA(x) CONV_FFMA(y) CONV_FFMA(z) CONV_FFMA(w)
        }
    }
    #pragma unroll
    for (int rr = 0; rr < 8; rr++) {
        int b = ty * 8 + rr;
        #pragma unroll
        for (int c = 0; c < 4; c++) {
            float2 v = up2(acc[rr][c]);
            #pragma unroll
            for (int l = 0; l < 2; l++) {
                int o = o0 + (c >> 1) * 64 + tx * 4 + (c & 1) * 2 + l;
                float cv = (l ? v.y : v.x) + bc[o];
                out[((size_t)b * TT + t) * HH + o] =
                    g_theme[((size_t)t * BB + b) * HH + o] * cv +
                    g_h[((size_t)t * BB + b) * HH + o];
            }
        }
    }
}

extern "C" void kernel_launch(void* const* d_in, const int* in_sizes, int n_in,
                              void* d_out, int out_size) {
    const float *x   = (const float *)d_in[0];
    const float *Wk  = (const float *)d_in[2];
    const float *bk  = (const float *)d_in[3];
    const float *Wr  = (const float *)d_in[4];
    const float *br  = (const float *)d_in[5];
    const float *Ws  = (const float *)d_in[6];
    const float *bs  = (const float *)d_in[7];
    const float *Wrs = (const float *)d_in[8];
    const float *brs = (const float *)d_in[9];
    const float *Wc  = (const float *)d_in[10];
    const float *bc  = (const float *)d_in[11];
    float *out = (float *)d_out;

    const int smem_bytes = (KH * 64 + KH * 36) * 4;  // 153600
    cudaFuncSetAttribute(phase1_main,
                         cudaFuncAttributeMaxDynamicSharedMemorySize, smem_bytes);

    wct_kernel<<<(CK * HH * HH + 255) / 256, 256>>>(Wc);
    xk_kernel<<<dim3(512, 13), 256>>>(x, Wk, bk, Wr, br);
    phase1_main<<<NBLK, 256, smem_bytes>>>(Wr);
    theme_kernel<<<dim3(TT, 16), 256>>>(Ws, bs, Wrs, brs);
    conv_kernel<<<dim3(TT, 3), 256>>>(bc, out);
}

// round 7
// speedup vs baseline: 1.2687x; 1.2687x over previous
#include <cuda_runtime.h>
#include <math.h>

#define BB 128
#define TT 512
#define DD 128
#define HH 384
#define GG 1542
#define GXP 1600        // padded g_xout row
#define GPAD 1664       // padded g_xk row (13 tiles of 128)
#define HSS 64
#define CK 10
#define GT 25           // phase1 g-tiles of 64
#define NBLK (GT * 4)   // 100 blocks
#define KH 384

__device__ float g_h[(size_t)TT * BB * HH];
__device__ float g_c[BB * HH];
__device__ float g_xout[BB * GXP];
__device__ float g_dist[TT * BB];
__device__ float g_theme[(size_t)TT * BB * HH];
__device__ float g_wct[CK * HH * HH];
__device__ float g_xk[(size_t)TT * BB * GPAD];
__device__ unsigned g_cnt2[4];
__device__ volatile unsigned g_gen2[4];

typedef unsigned long long u64;
__device__ __forceinline__ u64 pk2(float a, float b) {
    u64 r; asm("mov.b64 %0,{%1,%2};" : "=l"(r) : "f"(a), "f"(b)); return r;
}
__device__ __forceinline__ void fma2(u64 &d, u64 a, u64 b) {
    asm("fma.rn.f32x2 %0,%1,%2,%0;" : "+l"(d) : "l"(a), "l"(b));
}
__device__ __forceinline__ float2 up2(u64 v) {
    float2 r; asm("mov.b64 {%0,%1},%2;" : "=f"(r.x), "=f"(r.y) : "l"(v)); return r;
}
__device__ __forceinline__ float ftanh(float x) {
    float y; asm("tanh.approx.f32 %0,%1;" : "=f"(y) : "f"(x)); return y;
}
__device__ __forceinline__ float sgm(float x) { return 0.5f * ftanh(0.5f * x) + 0.5f; }

__device__ __forceinline__ void group_bar(int grp) {
    __syncthreads();
    if (threadIdx.x == 0) {
        unsigned old = g_gen2[grp];
        __threadfence();
        if (atomicAdd(&g_cnt2[grp], 1u) == GT - 1) {
            g_cnt2[grp] = 0;
            __threadfence();
            g_gen2[grp] = old + 1;
        } else {
            while (g_gen2[grp] == old) { }
            __threadfence();
        }
    }
    __syncthreads();
}

__device__ __forceinline__ void calc_dis(int t, int b, float *dis) {
    float cs = 0.f, c[CK];
    #pragma unroll
    for (int k = 0; k < CK; k++) {
        int s = t - (CK - 1) + k;
        cs += (s >= 0) ? g_dist[s * BB + b] : 0.f;
        c[k] = cs;
    }
    float mx = c[0];
    #pragma unroll
    for (int k = 1; k < CK; k++) mx = fmaxf(mx, c[k]);
    float sum = 0.f;
    #pragma unroll
    for (int k = 0; k < CK; k++) { c[k] = __expf(c[k] - mx); sum += c[k]; }
    float is = 1.f / sum;
    #pragma unroll
    for (int k = 0; k < CK; k++) dis[k] = c[k] * is;
}

__global__ void zero_c_kernel() {
    int i = blockIdx.x * 256 + threadIdx.x;
    if (i < BB * HH) g_c[i] = 0.f;
}

// Wc[o][i][k] -> g_wct[k][i][o]
__global__ void wct_kernel(const float * __restrict__ Wc) {
    int e = blockIdx.x * 256 + threadIdx.x;
    if (e < CK * HH * HH) {
        int o = e % HH, i = (e / HH) % HH, k = e / (HH * HH);
        g_wct[e] = Wc[((size_t)o * HH + i) * CK + k];
    }
}

// ---------- XK precompute: g_xk[t][b][g] = x[b,t]@Wk + (bk+br+Wk[D]+Wr[H]) ----------
#define XK_FFMA(COMP)                                                       \
    {                                                                       \
        ulonglong2 b0v = *(const ulonglong2 *)&Bs[kk][tx * 4];              \
        ulonglong2 b1v = *(const ulonglong2 *)&Bs[kk][tx * 4 + 64];         \
        _Pragma("unroll")                                                   \
        for (int rr = 0; rr < 8; rr++) {                                    \
            float av = a4[rr].COMP;                                         \
            u64 aa = pk2(av, av);                                           \
            fma2(acc[rr][0], aa, b0v.x); fma2(acc[rr][1], aa, b0v.y);       \
            fma2(acc[rr][2], aa, b1v.x); fma2(acc[rr][3], aa, b1v.y);       \
        }                                                                   \
        kk++;                                                               \
    }

__global__ __launch_bounds__(256) void xk_kernel(
    const float * __restrict__ x, const float * __restrict__ Wk,
    const float * __restrict__ bk, const float * __restrict__ Wr,
    const float * __restrict__ br)
{
    int b = blockIdx.x >> 2, t0 = (blockIdx.x & 3) * 128;
    int g0 = blockIdx.y * 128;
    int tid = threadIdx.x, tx = tid & 15, ty = tid >> 4;
    __shared__ __align__(16) float As[128][20];
    __shared__ __align__(16) float Bs[16][128];

    u64 acc[8][4];
    #pragma unroll
    for (int a = 0; a < 8; a++)
        #pragma unroll
        for (int c = 0; c < 4; c++) acc[a][c] = 0ull;

    for (int ch = 0; ch < 8; ch++) {
        int k0 = ch * 16;
        __syncthreads();
        #pragma unroll
        for (int l = 0; l < 8; l++) {
            int e = tid + l * 256;
            As[e >> 4][e & 15] = x[((size_t)b * TT + t0 + (e >> 4)) * DD + k0 + (e & 15)];
            int g = g0 + (e & 127);
            Bs[e >> 7][e & 127] = (g < GG) ? Wk[(size_t)(k0 + (e >> 7)) * GG + g] : 0.f;
        }
        __syncthreads();
        #pragma unroll
        for (int kq = 0; kq < 4; kq++) {
            float4 a4[8];
            #pragma unroll
            for (int rr = 0; rr < 8; rr++)
                a4[rr] = *(const float4 *)&As[ty * 8 + rr][kq * 4];
            int kk = kq * 4;
            XK_FFMA(x) XK_FFMA(y) XK_FFMA(z) XK_FFMA(w)
        }
    }
    #pragma unroll
    for (int rr = 0; rr < 8; rr++) {
        int t = t0 + ty * 8 + rr;
        #pragma unroll
        for (int c = 0; c < 4; c++) {
            float2 v = up2(acc[rr][c]);
            #pragma unroll
            for (int l = 0; l < 2; l++) {
                int g = g0 + (c >> 1) * 64 + tx * 4 + (c & 1) * 2 + l;
                if (g < GG) {
                    float bias = bk[g] + br[g] + Wk[(size_t)DD * GG + g] + Wr[(size_t)HH * GG + g];
                    g_xk[((size_t)t * BB + b) * GPAD + g] = (l ? v.y : v.x) + bias;
                }
            }
        }
    }
}

// ---------- Persistent phase-1: recurrent GEMM (K=384) + state update ----------
__global__ __launch_bounds__(256, 1) void phase1_main(const float * __restrict__ Wr)
{
    extern __shared__ float sm[];
    float *Bs = sm;                  // [384][64]
    float *As = sm + KH * 64;        // [384][36], reused for reduction + result

    int tid = threadIdx.x, blk = blockIdx.x;
    int gt = blk % GT, bt = blk / GT;
    int g0 = gt * 64, b0 = bt * 32;

    for (int j = 0; j < (KH * 64) / 256; j++) {
        int e = tid + j * 256;
        int gg = e & 63, k = e >> 6, g = g0 + gg;
        Bs[e] = (g < GG) ? Wr[(size_t)k * GG + g] : 0.f;
    }
    __syncthreads();

    int kc = tid >> 6, r = tid & 63;
    int tx = r & 7, ty = r >> 3;
    int sb = tid >> 3, sj = tid & 7;

    for (int t = 0; t < TT; t++) {
        #pragma unroll
        for (int j = 0; j < 12; j++) {
            int k4 = (sj + j * 8) * 4;
            float4 v;
            if (t > 0) v = *(const float4 *)&g_h[((size_t)(t - 1) * BB + b0 + sb) * HH + k4];
            else { v.x = v.y = v.z = v.w = 0.f; }
            As[(k4 + 0) * 36 + sb] = v.x;
            As[(k4 + 1) * 36 + sb] = v.y;
            As[(k4 + 2) * 36 + sb] = v.z;
            As[(k4 + 3) * 36 + sb] = v.w;
        }
        __syncthreads();

        u64 acc[4][4];
        #pragma unroll
        for (int a = 0; a < 4; a++)
            #pragma unroll
            for (int c = 0; c < 4; c++) acc[a][c] = 0ull;

        int kbeg = kc * (KH / 4);
        #pragma unroll 6
        for (int kk = kbeg; kk < kbeg + KH / 4; kk++) {
            float4 av = *(const float4 *)&As[kk * 36 + ty * 4];
            ulonglong2 bv0 = *(const ulonglong2 *)&Bs[kk * 64 + tx * 4];
            ulonglong2 bv1 = *(const ulonglong2 *)&Bs[kk * 64 + tx * 4 + 32];
            u64 aa;
            aa = pk2(av.x, av.x);
            fma2(acc[0][0], aa, bv0.x); fma2(acc[0][1], aa, bv0.y);
            fma2(acc[0][2], aa, bv1.x); fma2(acc[0][3], aa, bv1.y);
            aa = pk2(av.y, av.y);
            fma2(acc[1][0], aa, bv0.x); fma2(acc[1][1], aa, bv0.y);
            fma2(acc[1][2], aa, bv1.x); fma2(acc[1][3], aa, bv1.y);
            aa = pk2(av.z, av.z);
            fma2(acc[2][0], aa, bv0.x); fma2(acc[2][1], aa, bv0.y);
            fma2(acc[2][2], aa, bv1.x); fma2(acc[2][3], aa, bv1.y);
            aa = pk2(av.w, av.w);
            fma2(acc[3][0], aa, bv0.x); fma2(acc[3][1], aa, bv0.y);
            fma2(acc[3][2], aa, bv1.x); fma2(acc[3][3], aa, bv1.y);
        }
        __syncthreads();

        u64 *red = (u64 *)As;
        float *res = (float *)(red + 3 * 64 * 16);   // [32][64]
        if (kc) {
            #pragma unroll
            for (int a = 0; a < 4; a++)
                #pragma unroll
                for (int c = 0; c < 4; c++)
                    red[((size_t)(kc - 1) * 64 + r) * 16 + a * 4 + c] = acc[a][c];
        }
        __syncthreads();
        if (!kc) {
            #pragma unroll
            for (int a = 0; a < 4; a++) {
                #pragma unroll
                for (int c = 0; c < 4; c++) {
                    float2 s = up2(acc[a][c]);
                    #pragma unroll
                    for (int q = 0; q < 3; q++) {
                        float2 o = up2(red[((size_t)q * 64 + r) * 16 + a * 4 + c]);
                        s.x += o.x; s.y += o.y;
                    }
                    int gg = (c >> 1) * 32 + tx * 4 + (c & 1) * 2;
                    res[(ty * 4 + a) * 64 + gg] = s.x;
                    res[(ty * 4 + a) * 64 + gg + 1] = s.y;
                }
            }
        }
        __syncthreads();
        // cooperative coalesced epilogue: add xk, write g_xout (padded rows)
        #pragma unroll
        for (int j = 0; j < 2; j++) {
            int e = tid + j * 256;           // 0..511 float4s
            int b = e >> 4, q4 = e & 15;
            float4 v = ((const float4 *)res)[e];
            const float4 xk = *(const float4 *)&g_xk[((size_t)t * BB + b0 + b) * GPAD + g0 + q4 * 4];
            v.x += xk.x; v.y += xk.y; v.z += xk.z; v.w += xk.w;
            *(float4 *)&g_xout[(size_t)(b0 + b) * GXP + g0 + q4 * 4] = v;
        }
        group_bar(bt);

        // fused state update for this group's 32 b
        for (int el = gt * 256 + tid; el < 32 * HH; el += GT * 256) {
            int b = b0 + el / HH, i = el % HH;
            const float *xo = g_xout + (size_t)b * GXP;
            float z0 = xo[0], z1 = xo[1], z2 = xo[2];
            float m = fmaxf(z0, fmaxf(z1, z2));
            float e0 = __expf(z0 - m), e1 = __expf(z1 - m), e2 = __expf(z2 - m);
            float inv = 1.f / (e0 + e1 + e2);
            float fm0 = e0 * inv, fm1 = fm0 + e1 * inv, fm2 = fm1 + e2 * inv;
            float y0 = xo[3], y1 = xo[4], y2 = xo[5];
            float mi = fmaxf(y0, fmaxf(y1, y2));
            float q0 = __expf(y0 - mi), q1 = __expf(y1 - mi), q2 = __expf(y2 - mi);
            float iv = 1.f / (q0 + q1 + q2);
            float im2 = q2 * iv, im1 = im2 + q1 * iv, im0 = im1 + q0 * iv;
            int l = i >> 7;
            float fm = (l == 0) ? fm0 : (l == 1 ? fm1 : fm2);
            float im = (l == 0) ? im0 : (l == 1 ? im1 : im2);
            float fg = sgm(xo[6 + i]);
            float ig = sgm(xo[6 + HH + i]);
            float og = sgm(xo[6 + 2 * HH + i]);
            float ci = ftanh(xo[6 + 3 * HH + i]);
            float ov = fm * im;
            int e = b * HH + i;
            float cn = g_c[e] * (ov * fg + fm - ov) + ci * (ov * ig + im - ov);
            g_c[e] = cn;
            g_h[(size_t)t * BB * HH + e] = og * ftanh(cn);
            if (i == 0) g_dist[t * BB + b] = 1.f - (fm0 + fm1 + fm2) * (1.f / 3.f);
        }
        group_bar(bt);
    }
}

// ---------- theme ----------
__global__ __launch_bounds__(256) void theme_kernel(
    const float * __restrict__ Ws, const float * __restrict__ bs,
    const float * __restrict__ Wrs, const float * __restrict__ brs)
{
    int t = blockIdx.x, b0 = blockIdx.y * 8, tid = threadIdx.x;
    __shared__ float dis_s[8][CK], wm[8][HH], s1[8][HSS];
    if (tid < 8) calc_dis(t, b0 + tid, dis_s[tid]);
    __syncthreads();
    #pragma unroll
    for (int j = 0; j < 12; j++) {
        int e = tid + j * 256, b = e / HH, i = e % HH;
        float a = 0.f;
        #pragma unroll
        for (int k = 0; k < CK; k++) {
            int s = t - (CK - 1) + k;
            if (s >= 0) a += dis_s[b][k] * g_h[((size_t)s * BB + b0 + b) * HH + i];
        }
        wm[b][i] = a * (1.f / CK);
    }
    __syncthreads();
    #pragma unroll
    for (int j = 0; j < 2; j++) {
        int e = tid + j * 256, b = e / HSS, hs = e % HSS;
        float a = 0.f;
        for (int i = 0; i < HH; i++) a += wm[b][i] * Ws[i * HSS + hs];
        s1[b][hs] = fmaxf(a + bs[hs], 0.f);
    }
    __syncthreads();
    #pragma unroll
    for (int j = 0; j < 12; j++) {
        int e = tid + j * 256, b = e / HH, o = e % HH;
        float a = 0.f;
        #pragma unroll
        for (int hs = 0; hs < HSS; hs++) a += s1[b][hs] * Wrs[hs * HH + o];
        g_theme[((size_t)t * BB + b0 + b) * HH + o] = sgm(a + brs[o]);
    }
}

// ---------- conv + fused epilogue: K-chunks of 32, float4 staging ----------
#define CONV_FFMA(COMP)                                                     \
    {                                                                       \
        ulonglong2 b0v = *(const ulonglong2 *)&Bs[kk][tx * 4];              \
        ulonglong2 b1v = *(const ulonglong2 *)&Bs[kk][tx * 4 + 64];         \
        _Pragma("unroll")                                                   \
        for (int rr = 0; rr < 8; rr++) {                                    \
            float av = a4[rr].COMP;                                         \
            u64 aa = pk2(av, av);                                           \
            fma2(acc[rr][0], aa, b0v.x); fma2(acc[rr][1], aa, b0v.y);       \
            fma2(acc[rr][2], aa, b1v.x); fma2(acc[rr][3], aa, b1v.y);       \
        }                                                                   \
        kk++;                                                               \
    }

__global__ __launch_bounds__(256) void conv_kernel(const float * __restrict__ bc,
                                                   float * __restrict__ out)
{
    int t = blockIdx.x, o0 = blockIdx.y * 128, tid = threadIdx.x;
    int tx = tid & 15, ty = tid >> 4;
    __shared__ float dis_s[BB][CK];
    __shared__ __align__(16) float As[BB][36];   // 32 K + pad
    __shared__ __align__(16) float Bs[32][128];
    if (tid < BB) calc_dis(t, tid, dis_s[tid]);
    __syncthreads();

    u64 acc[8][4];
    #pragma unroll
    for (int a = 0; a < 8; a++)
        #pragma unroll
        for (int c = 0; c < 4; c++) acc[a][c] = 0ull;

    const int NCH = CK * (HH / 32);  // 120
    float4 pa[4], pb[4];
    {
        int s = t - (CK - 1);
        #pragma unroll
        for (int l = 0; l < 4; l++) {
            int f = tid + l * 256;
            int ab = f >> 3, ai = (f & 7) * 4;
            pa[l].x = pa[l].y = pa[l].z = pa[l].w = 0.f;
            if (s >= 0) pa[l] = *(const float4 *)&g_h[((size_t)s * BB + ab) * HH + ai];
            int br_ = f >> 5, bo = (f & 31) * 4;
            pb[l] = *(const float4 *)&g_wct[(size_t)br_ * HH + o0 + bo];
        }
    }
    for (int ch = 0; ch < NCH; ch++) {
        int k = ch / 12;
        __syncthreads();
        #pragma unroll
        for (int l = 0; l < 4; l++) {
            int f = tid + l * 256;
            int ab = f >> 3, ai = (f & 7) * 4;
            float d = dis_s[ab][k];
            float4 v = pa[l];
            v.x *= d; v.y *= d; v.z *= d; v.w *= d;
            *(float4 *)&As[ab][ai] = v;
            int br_ = f >> 5, bo = (f & 31) * 4;
            *(float4 *)&Bs[br_][bo] = pb[l];
        }
        __syncthreads();
        if (ch + 1 < NCH) {
            int k2 = (ch + 1) / 12, i0 = ((ch + 1) % 12) * 32, s = t - (CK - 1) + k2;
            #pragma unroll
            for (int l = 0; l < 4; l++) {
                int f = tid + l * 256;
                int ab = f >> 3, ai = (f & 7) * 4;
                pa[l].x = pa[l].y = pa[l].z = pa[l].w = 0.f;
                if (s >= 0) pa[l] = *(const float4 *)&g_h[((size_t)s * BB + ab) * HH + i0 + ai];
                int br_ = f >> 5, bo = (f & 31) * 4;
                pb[l] = *(const float4 *)&g_wct[((size_t)k2 * HH + i0 + br_) * HH + o0 + bo];
            }
        }
        #pragma unroll
        for (int kq = 0; kq < 8; kq++) {
            float4 a4[8];
            #pragma unroll
            for (int rr = 0; rr < 8; rr++)
                a4[rr] = *(const float4 *)&As[ty * 8 + rr][kq * 4];
            int kk = kq * 4;
            CONV_FFMA(x) CONV_FFMA(y) CONV_FFMA(z) CONV_FFMA(w)
        }
    }
    #pragma unroll
    for (int rr = 0; rr < 8; rr++) {
        int b = ty * 8 + rr;
        #pragma unroll
        for (int c = 0; c < 4; c++) {
            float2 v = up2(acc[rr][c]);
            #pragma unroll
            for (int l = 0; l < 2; l++) {
                int o = o0 + (c >> 1) * 64 + tx * 4 + (c & 1) * 2 + l;
                float cv = (l ? v.y : v.x) + bc[o];
                out[((size_t)b * TT + t) * HH + o] =
                    g_theme[((size_t)t * BB + b) * HH + o] * cv +
                    g_h[((size_t)t * BB + b) * HH + o];
            }
        }
    }
}

extern "C" void kernel_launch(void* const* d_in, const int* in_sizes, int n_in,
                              void* d_out, int out_size) {
    const float *x   = (const float *)d_in[0];
    const float *Wk  = (const float *)d_in[2];
    const float *bk  = (const float *)d_in[3];
    const float *Wr  = (const float *)d_in[4];
    const float *br  = (const float *)d_in[5];
    const float *Ws  = (const float *)d_in[6];
    const float *bs  = (const float *)d_in[7];
    const float *Wrs = (const float *)d_in[8];
    const float *brs = (const float *)d_in[9];
    const float *Wc  = (const float *)d_in[10];
    const float *bc  = (const float *)d_in[11];
    float *out = (float *)d_out;

    const int smem_bytes = (KH * 64 + KH * 36) * 4;  // 153600
    cudaFuncSetAttribute(phase1_main,
                         cudaFuncAttributeMaxDynamicSharedMemorySize, smem_bytes);

    xk_kernel<<<dim3(512, 13), 256>>>(x, Wk, bk, Wr, br);          // #1
    wct_kernel<<<(CK * HH * HH + 255) / 256, 256>>>(Wc);           // #2
    zero_c_kernel<<<(BB * HH + 255) / 256, 256>>>();               // #3
    phase1_main<<<NBLK, 256, smem_bytes>>>(Wr);                    // #4 (ncu target)
    theme_kernel<<<dim3(TT, 16), 256>>>(Ws, bs, Wrs, brs);         // #5
    conv_kernel<<<dim3(TT, 3), 256>>>(bc, out);                    // #6
}

// round 9
// speedup vs baseline: 1.3315x; 1.0495x over previous
#include <cuda_runtime.h>
#include <math.h>

#define BB 128
#define TT 512
#define DD 128
#define HH 384
#define GG 1542
#define GXP 1600
#define GPAD 1664
#define HSS 64
#define CK 10
#define GT 25
#define NBLK (GT * 4)
#define KH 384
#define APAD 40   // A-staging row pad: 40 floats = 160B, 16B-aligned for LD.128

__device__ float g_h[(size_t)TT * BB * HH];
__device__ float g_c[BB * HH];
__device__ float g_xout[BB * GXP];
__device__ float g_dist[TT * BB];
__device__ float g_theme[(size_t)TT * BB * HH];
__device__ float g_wct[CK * HH * HH];
__device__ float g_xk[(size_t)TT * BB * GPAD];
__device__ unsigned g_cnt2[4];
__device__ volatile unsigned g_gen2[4];

typedef unsigned long long u64;
__device__ __forceinline__ u64 pk2(float a, float b) {
    u64 r; asm("mov.b64 %0,{%1,%2};" : "=l"(r) : "f"(a), "f"(b)); return r;
}
__device__ __forceinline__ void fma2(u64 &d, u64 a, u64 b) {
    asm("fma.rn.f32x2 %0,%1,%2,%0;" : "+l"(d) : "l"(a), "l"(b));
}
__device__ __forceinline__ float2 up2(u64 v) {
    float2 r; asm("mov.b64 {%0,%1},%2;" : "=f"(r.x), "=f"(r.y) : "l"(v)); return r;
}
__device__ __forceinline__ float ftanh(float x) {
    float y; asm("tanh.approx.f32 %0,%1;" : "=f"(y) : "f"(x)); return y;
}
__device__ __forceinline__ float sgm(float x) { return 0.5f * ftanh(0.5f * x) + 0.5f; }

__device__ __forceinline__ void group_bar(int grp) {
    __syncthreads();
    if (threadIdx.x == 0) {
        unsigned old = g_gen2[grp];
        __threadfence();
        if (atomicAdd(&g_cnt2[grp], 1u) == GT - 1) {
            g_cnt2[grp] = 0;
            __threadfence();
            g_gen2[grp] = old + 1;
        } else {
            while (g_gen2[grp] == old) { }
            __threadfence();
        }
    }
    __syncthreads();
}

__device__ __forceinline__ void calc_dis(int t, int b, float *dis) {
    float cs = 0.f, c[CK];
    #pragma unroll
    for (int k = 0; k < CK; k++) {
        int s = t - (CK - 1) + k;
        cs += (s >= 0) ? g_dist[s * BB + b] : 0.f;
        c[k] = cs;
    }
    float mx = c[0];
    #pragma unroll
    for (int k = 1; k < CK; k++) mx = fmaxf(mx, c[k]);
    float sum = 0.f;
    #pragma unroll
    for (int k = 0; k < CK; k++) { c[k] = __expf(c[k] - mx); sum += c[k]; }
    float is = 1.f / sum;
    #pragma unroll
    for (int k = 0; k < CK; k++) dis[k] = c[k] * is;
}

__global__ void zero_c_kernel() {
    int i = blockIdx.x * 256 + threadIdx.x;
    if (i < BB * HH) g_c[i] = 0.f;
}

__global__ void wct_kernel(const float * __restrict__ Wc) {
    int e = blockIdx.x * 256 + threadIdx.x;
    if (e < CK * HH * HH) {
        int o = e % HH, i = (e / HH) % HH, k = e / (HH * HH);
        g_wct[e] = Wc[((size_t)o * HH + i) * CK + k];
    }
}

// ---------- XK precompute ----------
#define XK_FFMA(COMP)                                                       \
    {                                                                       \
        ulonglong2 b0v = *(const ulonglong2 *)&Bs[kk][tx * 4];              \
        ulonglong2 b1v = *(const ulonglong2 *)&Bs[kk][tx * 4 + 64];         \
        _Pragma("unroll")                                                   \
        for (int rr = 0; rr < 8; rr++) {                                    \
            float av = a4[rr].COMP;                                         \
            u64 aa = pk2(av, av);                                           \
            fma2(acc[rr][0], aa, b0v.x); fma2(acc[rr][1], aa, b0v.y);       \
            fma2(acc[rr][2], aa, b1v.x); fma2(acc[rr][3], aa, b1v.y);       \
        }                                                                   \
        kk++;                                                               \
    }

__global__ __launch_bounds__(256) void xk_kernel(
    const float * __restrict__ x, const float * __restrict__ Wk,
    const float * __restrict__ bk, const float * __restrict__ Wr,
    const float * __restrict__ br)
{
    int b = blockIdx.x >> 2, t0 = (blockIdx.x & 3) * 128;
    int g0 = blockIdx.y * 128;
    int tid = threadIdx.x, tx = tid & 15, ty = tid >> 4;
    __shared__ __align__(16) float As[128][20];
    __shared__ __align__(16) float Bs[16][128];

    u64 acc[8][4];
    #pragma unroll
    for (int a = 0; a < 8; a++)
        #pragma unroll
        for (int c = 0; c < 4; c++) acc[a][c] = 0ull;

    for (int ch = 0; ch < 8; ch++) {
        int k0 = ch * 16;
        __syncthreads();
        #pragma unroll
        for (int l = 0; l < 8; l++) {
            int e = tid + l * 256;
            As[e >> 4][e & 15] = x[((size_t)b * TT + t0 + (e >> 4)) * DD + k0 + (e & 15)];
            int g = g0 + (e & 127);
            Bs[e >> 7][e & 127] = (g < GG) ? Wk[(size_t)(k0 + (e >> 7)) * GG + g] : 0.f;
        }
        __syncthreads();
        #pragma unroll
        for (int kq = 0; kq < 4; kq++) {
            float4 a4[8];
            #pragma unroll
            for (int rr = 0; rr < 8; rr++)
                a4[rr] = *(const float4 *)&As[ty * 8 + rr][kq * 4];
            int kk = kq * 4;
            XK_FFMA(x) XK_FFMA(y) XK_FFMA(z) XK_FFMA(w)
        }
    }
    #pragma unroll
    for (int rr = 0; rr < 8; rr++) {
        int t = t0 + ty * 8 + rr;
        #pragma unroll
        for (int c = 0; c < 4; c++) {
            float2 v = up2(acc[rr][c]);
            #pragma unroll
            for (int l = 0; l < 2; l++) {
                int g = g0 + (c >> 1) * 64 + tx * 4 + (c & 1) * 2 + l;
                if (g < GG) {
                    float bias = bk[g] + br[g] + Wk[(size_t)DD * GG + g] + Wr[(size_t)HH * GG + g];
                    g_xk[((size_t)t * BB + b) * GPAD + g] = (l ? v.y : v.x) + bias;
                }
            }
        }
    }
}

// ---------- Persistent phase-1: 512 threads, 4-way split-K ----------
__global__ __launch_bounds__(512, 1) void phase1_main(const float * __restrict__ Wr)
{
    extern __shared__ float sm[];
    float *Bs = sm;                  // [384][64]
    float *As = sm + KH * 64;        // [384][APAD] staging; aliased red/res

    int tid = threadIdx.x, blk = blockIdx.x;
    int gt = blk % GT, bt = blk / GT;
    int g0 = gt * 64, b0 = bt * 32;

    for (int j = 0; j < (KH * 64) / 512; j++) {
        int e = tid + j * 512;
        int gg = e & 63, k = e >> 6, g = g0 + gg;
        Bs[e] = (g < GG) ? Wr[(size_t)k * GG + g] : 0.f;
    }
    __syncthreads();

    int kc = tid >> 7, r = tid & 127;
    int tx = r & 15, ty = r >> 4;    // tx: g-quad (16), ty: b-quad (8)
    int sb = tid >> 4, sj = tid & 15;
    int eb = tid >> 4, eq = tid & 15;   // epilogue: one float4 per thread

    for (int t = 0; t < TT; t++) {
        // prefetch epilogue xk early (DRAM latency hidden behind GEMM)
        float4 xk = *(const float4 *)&g_xk[((size_t)t * BB + b0 + eb) * GPAD + g0 + eq * 4];

        // stage h_{t-1}[32][384] into As[k][b]
        #pragma unroll
        for (int j = 0; j < 6; j++) {
            int k4 = (sj + j * 16) * 4;
            float4 v;
            if (t > 0) v = *(const float4 *)&g_h[((size_t)(t - 1) * BB + b0 + sb) * HH + k4];
            else { v.x = v.y = v.z = v.w = 0.f; }
            As[(k4 + 0) * APAD + sb] = v.x;
            As[(k4 + 1) * APAD + sb] = v.y;
            As[(k4 + 2) * APAD + sb] = v.z;
            As[(k4 + 3) * APAD + sb] = v.w;
        }
        __syncthreads();

        u64 acc[4][2];
        #pragma unroll
        for (int a = 0; a < 4; a++) { acc[a][0] = 0ull; acc[a][1] = 0ull; }

        int kbeg = kc * (KH / 4);
        #pragma unroll 6
        for (int kk = kbeg; kk < kbeg + KH / 4; kk++) {
            float4 av = *(const float4 *)&As[kk * APAD + ty * 4];
            ulonglong2 bv = *(const ulonglong2 *)&Bs[kk * 64 + tx * 4];
            u64 aa;
            aa = pk2(av.x, av.x); fma2(acc[0][0], aa, bv.x); fma2(acc[0][1], aa, bv.y);
            aa = pk2(av.y, av.y); fma2(acc[1][0], aa, bv.x); fma2(acc[1][1], aa, bv.y);
            aa = pk2(av.z, av.z); fma2(acc[2][0], aa, bv.x); fma2(acc[2][1], aa, bv.y);
            aa = pk2(av.w, av.w); fma2(acc[3][0], aa, bv.x); fma2(acc[3][1], aa, bv.y);
        }
        __syncthreads();

        ulonglong2 *red = (ulonglong2 *)As;          // [3][4][128] ull2
        float *res = (float *)(red + 3 * 512);       // [32][64]
        if (kc) {
            #pragma unroll
            for (int a = 0; a < 4; a++) {
                ulonglong2 v; v.x = acc[a][0]; v.y = acc[a][1];
                red[(size_t)(kc - 1) * 512 + a * 128 + r] = v;
            }
        }
        __syncthreads();
        if (!kc) {
            #pragma unroll
            for (int a = 0; a < 4; a++) {
                float2 s0 = up2(acc[a][0]), s1 = up2(acc[a][1]);
                #pragma unroll
                for (int q = 0; q < 3; q++) {
                    ulonglong2 v = red[(size_t)q * 512 + a * 128 + r];
                    float2 o0 = up2(v.x), o1 = up2(v.y);
                    s0.x += o0.x; s0.y += o0.y; s1.x += o1.x; s1.y += o1.y;
                }
                float4 w; w.x = s0.x; w.y = s0.y; w.z = s1.x; w.w = s1.y;
                *(float4 *)&res[(ty * 4 + a) * 64 + tx * 4] = w;
            }
        }
        __syncthreads();
        // coalesced epilogue: one float4 per thread
        {
            float4 v = ((const float4 *)res)[tid];
            v.x += xk.x; v.y += xk.y; v.z += xk.z; v.w += xk.w;
            *(float4 *)&g_xout[(size_t)(b0 + eb) * GXP + g0 + eq * 4] = v;
        }
        group_bar(bt);

        // fused state update for this group's 32 b (distributed over 25 blocks)
        for (int el = gt * 512 + tid; el < 32 * HH; el += GT * 512) {
            int b = b0 + el / HH, i = el % HH;
            const float *xo = g_xout + (size_t)b * GXP;
            float z0 = xo[0], z1 = xo[1], z2 = xo[2];
            float m = fmaxf(z0, fmaxf(z1, z2));
            float e0 = __expf(z0 - m), e1 = __expf(z1 - m), e2 = __expf(z2 - m);
            float inv = 1.f / (e0 + e1 + e2);
            float fm0 = e0 * inv, fm1 = fm0 + e1 * inv, fm2 = fm1 + e2 * inv;
            float y0 = xo[3], y1 = xo[4], y2 = xo[5];
            float mi = fmaxf(y0, fmaxf(y1, y2));
            float q0 = __expf(y0 - mi), q1 = __expf(y1 - mi), q2 = __expf(y2 - mi);
            float iv = 1.f / (q0 + q1 + q2);
            float im2 = q2 * iv, im1 = im2 + q1 * iv, im0 = im1 + q0 * iv;
            int l = i >> 7;
            float fm = (l == 0) ? fm0 : (l == 1 ? fm1 : fm2);
            float im = (l == 0) ? im0 : (l == 1 ? im1 : im2);
            float fg = sgm(xo[6 + i]);
            float ig = sgm(xo[6 + HH + i]);
            float og = sgm(xo[6 + 2 * HH + i]);
            float ci = ftanh(xo[6 + 3 * HH + i]);
            float ov = fm * im;
            int e = b * HH + i;
            float cn = g_c[e] * (ov * fg + fm - ov) + ci * (ov * ig + im - ov);
            g_c[e] = cn;
            g_h[(size_t)t * BB * HH + e] = og * ftanh(cn);
            if (i == 0) g_dist[t * BB + b] = 1.f - (fm0 + fm1 + fm2) * (1.f / 3.f);
        }
        group_bar(bt);
    }
}

// ---------- theme ----------
__global__ __launch_bounds__(256) void theme_kernel(
    const float * __restrict__ Ws, const float * __restrict__ bs,
    const float * __restrict__ Wrs, const float * __restrict__ brs)
{
    int t = blockIdx.x, b0 = blockIdx.y * 8, tid = threadIdx.x;
    __shared__ float dis_s[8][CK], wm[8][HH], s1[8][HSS];
    if (tid < 8) calc_dis(t, b0 + tid, dis_s[tid]);
    __syncthreads();
    #pragma unroll
    for (int j = 0; j < 12; j++) {
        int e = tid + j * 256, b = e / HH, i = e % HH;
        float a = 0.f;
        #pragma unroll
        for (int k = 0; k < CK; k++) {
            int s = t - (CK - 1) + k;
            if (s >= 0) a += dis_s[b][k] * g_h[((size_t)s * BB + b0 + b) * HH + i];
        }
        wm[b][i] = a * (1.f / CK);
    }
    __syncthreads();
    #pragma unroll
    for (int j = 0; j < 2; j++) {
        int e = tid + j * 256, b = e / HSS, hs = e % HSS;
        float a = 0.f;
        for (int i = 0; i < HH; i++) a += wm[b][i] * Ws[i * HSS + hs];
        s1[b][hs] = fmaxf(a + bs[hs], 0.f);
    }
    __syncthreads();
    #pragma unroll
    for (int j = 0; j < 12; j++) {
        int e = tid + j * 256, b = e / HH, o = e % HH;
        float a = 0.f;
        #pragma unroll
        for (int hs = 0; hs < HSS; hs++) a += s1[b][hs] * Wrs[hs * HH + o];
        g_theme[((size_t)t * BB + b0 + b) * HH + o] = sgm(a + brs[o]);
    }
}

// ---------- conv ----------
#define CONV_FFMA(COMP)                                                     \
    {                                                                       \
        ulonglong2 b0v = *(const ulonglong2 *)&Bs[kk][tx * 4];              \
        ulonglong2 b1v = *(const ulonglong2 *)&Bs[kk][tx * 4 + 64];         \
        _Pragma("unroll")                                                   \
        for (int rr = 0; rr < 8; rr++) {                                    \
            float av = a4[rr].COMP;                                         \
            u64 aa = pk2(av, av);                                           \
            fma2(acc[rr][0], aa, b0v.x); fma2(acc[rr][1], aa, b0v.y);       \
            fma2(acc[rr][2], aa, b1v.x); fma2(acc[rr][3], aa, b1v.y);       \
        }                                                                   \
        kk++;                                                               \
    }

__global__ __launch_bounds__(256) void conv_kernel(const float * __restrict__ bc,
                                                   float * __restrict__ out)
{
    int t = blockIdx.x, o0 = blockIdx.y * 128, tid = threadIdx.x;
    int tx = tid & 15, ty = tid >> 4;
    __shared__ float dis_s[BB][CK];
    __shared__ __align__(16) float As[BB][36];
    __shared__ __align__(16) float Bs[32][128];
    if (tid < BB) calc_dis(t, tid, dis_s[tid]);
    __syncthreads();

    u64 acc[8][4];
    #pragma unroll
    for (int a = 0; a < 8; a++)
        #pragma unroll
        for (int c = 0; c < 4; c++) acc[a][c] = 0ull;

    const int NCH = CK * (HH / 32);
    float4 pa[4], pb[4];
    {
        int s = t - (CK - 1);
        #pragma unroll
        for (int l = 0; l < 4; l++) {
            int f = tid + l * 256;
            int ab = f >> 3, ai = (f & 7) * 4;
            pa[l].x = pa[l].y = pa[l].z = pa[l].w = 0.f;
            if (s >= 0) pa[l] = *(const float4 *)&g_h[((size_t)s * BB + ab) * HH + ai];
            int br_ = f >> 5, bo = (f & 31) * 4;
            pb[l] = *(const float4 *)&g_wct[(size_t)br_ * HH + o0 + bo];
        }
    }
    for (int ch = 0; ch < NCH; ch++) {
        int k = ch / 12;
        __syncthreads();
        #pragma unroll
        for (int l = 0; l < 4; l++) {
            int f = tid + l * 256;
            int ab = f >> 3, ai = (f & 7) * 4;
            float d = dis_s[ab][k];
            float4 v = pa[l];
            v.x *= d; v.y *= d; v.z *= d; v.w *= d;
            *(float4 *)&As[ab][ai] = v;
            int br_ = f >> 5, bo = (f & 31) * 4;
            *(float4 *)&Bs[br_][bo] = pb[l];
        }
        __syncthreads();
        if (ch + 1 < NCH) {
            int k2 = (ch + 1) / 12, i0 = ((ch + 1) % 12) * 32, s = t - (CK - 1) + k2;
            #pragma unroll
            for (int l = 0; l < 4; l++) {
                int f = tid + l * 256;
                int ab = f >> 3, ai = (f & 7) * 4;
                pa[l].x = pa[l].y = pa[l].z = pa[l].w = 0.f;
                if (s >= 0) pa[l] = *(const float4 *)&g_h[((size_t)s * BB + ab) * HH + i0 + ai];
                int br_ = f >> 5, bo = (f & 31) * 4;
                pb[l] = *(const float4 *)&g_wct[((size_t)k2 * HH + i0 + br_) * HH + o0 + bo];
            }
        }
        #pragma unroll
        for (int kq = 0; kq < 8; kq++) {
            float4 a4[8];
            #pragma unroll
            for (int rr = 0; rr < 8; rr++)
                a4[rr] = *(const float4 *)&As[ty * 8 + rr][kq * 4];
            int kk = kq * 4;
            CONV_FFMA(x) CONV_FFMA(y) CONV_FFMA(z) CONV_FFMA(w)
        }
    }
    #pragma unroll
    for (int rr = 0; rr < 8; rr++) {
        int b = ty * 8 + rr;
        #pragma unroll
        for (int c = 0; c < 4; c++) {
            float2 v = up2(acc[rr][c]);
            #pragma unroll
            for (int l = 0; l < 2; l++) {
                int o = o0 + (c >> 1) * 64 + tx * 4 + (c & 1) * 2 + l;
                float cv = (l ? v.y : v.x) + bc[o];
                out[((size_t)b * TT + t) * HH + o] =
                    g_theme[((size_t)t * BB + b) * HH + o] * cv +
                    g_h[((size_t)t * BB + b) * HH + o];
            }
        }
    }
}

extern "C" void kernel_launch(void* const* d_in, const int* in_sizes, int n_in,
                              void* d_out, int out_size) {
    const float *x   = (const float *)d_in[0];
    const float *Wk  = (const float *)d_in[2];
    const float *bk  = (const float *)d_in[3];
    const float *Wr  = (const float *)d_in[4];
    const float *br  = (const float *)d_in[5];
    const float *Ws  = (const float *)d_in[6];
    const float *bs  = (const float *)d_in[7];
    const float *Wrs = (const float *)d_in[8];
    const float *brs = (const float *)d_in[9];
    const float *Wc  = (const float *)d_in[10];
    const float *bc  = (const float *)d_in[11];
    float *out = (float *)d_out;

    const int smem_bytes = (KH * 64 + KH * APAD) * 4;  // 159744
    cudaFuncSetAttribute(phase1_main,
                         cudaFuncAttributeMaxDynamicSharedMemorySize, smem_bytes);

    xk_kernel<<<dim3(512, 13), 256>>>(x, Wk, bk, Wr, br);
    wct_kernel<<<(CK * HH * HH + 255) / 256, 256>>>(Wc);
    zero_c_kernel<<<(BB * HH + 255) / 256, 256>>>();
    phase1_main<<<NBLK, 512, smem_bytes>>>(Wr);
    theme_kernel<<<dim3(TT, 16), 256>>>(Ws, bs, Wrs, brs);
    conv_kernel<<<dim3(TT, 3), 256>>>(bc, out);
}

// round 10
// speedup vs baseline: 1.3999x; 1.0514x over previous
#include <cuda_runtime.h>
#include <math.h>

#define BB 128
#define TT 512
#define DD 128
#define HH 384
#define GG 1542
#define GPAD 1664
#define HSS 64
#define CK 10
#define GT 24           // blocks per group (one per 16-wide i-slice)
#define NBLK (GT * 4)   // 96 blocks
#define KH 384
#define APAD 40

__device__ float g_h[(size_t)TT * BB * HH];
__device__ float g_dist[TT * BB];
__device__ float g_theme[(size_t)TT * BB * HH];
__device__ float g_wct[CK * HH * HH];
__device__ float g_xk[(size_t)TT * BB * GPAD];   // [t][b][g'] g'=g-6 gates, 1536+g masters
__device__ unsigned g_cnt2[4];
__device__ volatile unsigned g_gen2[4];

typedef unsigned long long u64;
__device__ __forceinline__ u64 pk2(float a, float b) {
    u64 r; asm("mov.b64 %0,{%1,%2};" : "=l"(r) : "f"(a), "f"(b)); return r;
}
__device__ __forceinline__ void fma2(u64 &d, u64 a, u64 b) {
    asm("fma.rn.f32x2 %0,%1,%2,%0;" : "+l"(d) : "l"(a), "l"(b));
}
__device__ __forceinline__ float2 up2(u64 v) {
    float2 r; asm("mov.b64 {%0,%1},%2;" : "=f"(r.x), "=f"(r.y) : "l"(v)); return r;
}
__device__ __forceinline__ float ftanh(float x) {
    float y; asm("tanh.approx.f32 %0,%1;" : "=f"(y) : "f"(x)); return y;
}
__device__ __forceinline__ float sgm(float x) { return 0.5f * ftanh(0.5f * x) + 0.5f; }

__device__ __forceinline__ void group_bar(int grp) {
    __syncthreads();
    if (threadIdx.x == 0) {
        unsigned old = g_gen2[grp];
        __threadfence();
        if (atomicAdd(&g_cnt2[grp], 1u) == GT - 1) {
            g_cnt2[grp] = 0;
            __threadfence();
            g_gen2[grp] = old + 1;
        } else {
            while (g_gen2[grp] == old) { }
            __threadfence();
        }
    }
    __syncthreads();
}

__device__ __forceinline__ void calc_dis(int t, int b, float *dis) {
    float cs = 0.f, c[CK];
    #pragma unroll
    for (int k = 0; k < CK; k++) {
        int s = t - (CK - 1) + k;
        cs += (s >= 0) ? g_dist[s * BB + b] : 0.f;
        c[k] = cs;
    }
    float mx = c[0];
    #pragma unroll
    for (int k = 1; k < CK; k++) mx = fmaxf(mx, c[k]);
    float sum = 0.f;
    #pragma unroll
    for (int k = 0; k < CK; k++) { c[k] = __expf(c[k] - mx); sum += c[k]; }
    float is = 1.f / sum;
    #pragma unroll
    for (int k = 0; k < CK; k++) dis[k] = c[k] * is;
}

__global__ void wct_kernel(const float * __restrict__ Wc) {
    int e = blockIdx.x * 256 + threadIdx.x;
    if (e < CK * HH * HH) {
        int o = e % HH, i = (e / HH) % HH, k = e / (HH * HH);
        g_wct[e] = Wc[((size_t)o * HH + i) * CK + k];
    }
}

// ---------- XK precompute ----------
#define XK_FFMA(COMP)                                                       \
    {                                                                       \
        ulonglong2 b0v = *(const ulonglong2 *)&Bs[kk][tx * 4];              \
        ulonglong2 b1v = *(const ulonglong2 *)&Bs[kk][tx * 4 + 64];         \
        _Pragma("unroll")                                                   \
        for (int rr = 0; rr < 8; rr++) {                                    \
            float av = a4[rr].COMP;                                         \
            u64 aa = pk2(av, av);                                           \
            fma2(acc[rr][0], aa, b0v.x); fma2(acc[rr][1], aa, b0v.y);       \
            fma2(acc[rr][2], aa, b1v.x); fma2(acc[rr][3], aa, b1v.y);       \
        }                                                                   \
        kk++;                                                               \
    }

__global__ __launch_bounds__(256) void xk_kernel(
    const float * __restrict__ x, const float * __restrict__ Wk,
    const float * __restrict__ bk, const float * __restrict__ Wr,
    const float * __restrict__ br)
{
    int b = blockIdx.x >> 2, t0 = (blockIdx.x & 3) * 128;
    int g0 = blockIdx.y * 128;
    int tid = threadIdx.x, tx = tid & 15, ty = tid >> 4;
    __shared__ __align__(16) float As[128][20];
    __shared__ __align__(16) float Bs[16][128];

    u64 acc[8][4];
    #pragma unroll
    for (int a = 0; a < 8; a++)
        #pragma unroll
        for (int c = 0; c < 4; c++) acc[a][c] = 0ull;

    for (int ch = 0; ch < 8; ch++) {
        int k0 = ch * 16;
        __syncthreads();
        #pragma unroll
        for (int l = 0; l < 8; l++) {
            int e = tid + l * 256;
            As[e >> 4][e & 15] = x[((size_t)b * TT + t0 + (e >> 4)) * DD + k0 + (e & 15)];
            int g = g0 + (e & 127);
            Bs[e >> 7][e & 127] = (g < GG) ? Wk[(size_t)(k0 + (e >> 7)) * GG + g] : 0.f;
        }
        __syncthreads();
        #pragma unroll
        for (int kq = 0; kq < 4; kq++) {
            float4 a4[8];
            #pragma unroll
            for (int rr = 0; rr < 8; rr++)
                a4[rr] = *(const float4 *)&As[ty * 8 + rr][kq * 4];
            int kk = kq * 4;
            XK_FFMA(x) XK_FFMA(y) XK_FFMA(z) XK_FFMA(w)
        }
    }
    #pragma unroll
    for (int rr = 0; rr < 8; rr++) {
        int t = t0 + ty * 8 + rr;
        #pragma unroll
        for (int c = 0; c < 4; c++) {
            float2 v = up2(acc[rr][c]);
            #pragma unroll
            for (int l = 0; l < 2; l++) {
                int g = g0 + (c >> 1) * 64 + tx * 4 + (c & 1) * 2 + l;
                if (g < GG) {
                    float bias = bk[g] + br[g] + Wk[(size_t)DD * GG + g] + Wr[(size_t)HH * GG + g];
                    int gp = (g < 6) ? (1536 + g) : (g - 6);
                    g_xk[((size_t)t * BB + b) * GPAD + gp] = (l ? v.y : v.x) + bias;
                }
            }
        }
    }
}

// ---------- Persistent phase-1: block-local update, 1 barrier/step ----------
// Block (gt, bt): columns {6+384q+16*gt+m} (all 4 gates for i-slice gt) + 6 masters.
__global__ __launch_bounds__(512, 1) void phase1_main(const float * __restrict__ Wr)
{
    extern __shared__ float sm[];
    float *Bs   = sm;                    // [384][64] gate weights
    float *Bsm  = Bs + KH * 64;          // [384][8]  master weights (pad 8)
    float *As   = Bsm + KH * 8;          // [384][APAD]; aliased red+res after GEMM
    float *Msum = As + KH * APAD;        // [4][192] master partials
    float *fms  = Msum + 4 * 192;        // [32][3]
    float *ims  = fms + 96;              // [32][3]

    int tid = threadIdx.x, blk = blockIdx.x;
    int gt = blk % GT, bt = blk / GT;
    int b0 = bt * 32;

    for (int j = 0; j < (KH * 64) / 512; j++) {
        int e = tid + j * 512;
        int gg = e & 63, k = e >> 6, q = gg >> 4, m = gg & 15;
        Bs[e] = Wr[(size_t)k * GG + 6 + 384 * q + 16 * gt + m];
    }
    for (int e = tid; e < KH * 8; e += 512) {
        int g = e & 7, k = e >> 3;
        Bsm[e] = (g < 6) ? Wr[(size_t)k * GG + g] : 0.f;
    }
    __syncthreads();

    int kc = tid >> 7, r = tid & 127;
    int tx = r & 15, ty = r >> 4;
    int sb = tid >> 4, sj = tid & 15;
    int ub = tid >> 4, um = tid & 15;        // update element (b, m)
    int ui = gt * 16 + um, ul = ui >> 7;     // i, level
    float creg = 0.f;

    int mid0 = 2 * r, mb = mid0 / 6, mg0 = mid0 % 6;   // master dot pair (r<96)

    for (int t = 0; t < TT; t++) {
        // register prefetches (DRAM latency hidden behind staging+GEMM)
        float4 xkp[4];
        if (kc == 0) {
            int gp = 384 * (tx >> 2) + 16 * gt + (tx & 3) * 4;
            #pragma unroll
            for (int a = 0; a < 4; a++)
                xkp[a] = *(const float4 *)&g_xk[((size_t)t * BB + b0 + ty * 4 + a) * GPAD + gp];
        }
        float xkm[6];
        if (tid >= 128 && tid < 160) {
            int b = tid - 128;
            float4 v4 = *(const float4 *)&g_xk[((size_t)t * BB + b0 + b) * GPAD + 1536];
            float2 v2 = *(const float2 *)&g_xk[((size_t)t * BB + b0 + b) * GPAD + 1540];
            xkm[0] = v4.x; xkm[1] = v4.y; xkm[2] = v4.z; xkm[3] = v4.w;
            xkm[4] = v2.x; xkm[5] = v2.y;
        }

        // stage h_{t-1}[32][384] into As[k][b]
        #pragma unroll
        for (int j = 0; j < 6; j++) {
            int k4 = (sj + j * 16) * 4;
            float4 v;
            if (t > 0) v = *(const float4 *)&g_h[((size_t)(t - 1) * BB + b0 + sb) * HH + k4];
            else { v.x = v.y = v.z = v.w = 0.f; }
            As[(k4 + 0) * APAD + sb] = v.x;
            As[(k4 + 1) * APAD + sb] = v.y;
            As[(k4 + 2) * APAD + sb] = v.z;
            As[(k4 + 3) * APAD + sb] = v.w;
        }
        __syncthreads();

        // main gate GEMM (split-K 4, micro 4b x 4g)
        u64 acc[4][2];
        #pragma unroll
        for (int a = 0; a < 4; a++) { acc[a][0] = 0ull; acc[a][1] = 0ull; }
        int kbeg = kc * (KH / 4);
        #pragma unroll 6
        for (int kk = kbeg; kk < kbeg + KH / 4; kk++) {
            float4 av = *(const float4 *)&As[kk * APAD + ty * 4];
            ulonglong2 bv = *(const ulonglong2 *)&Bs[kk * 64 + tx * 4];
            u64 aa;
            aa = pk2(av.x, av.x); fma2(acc[0][0], aa, bv.x); fma2(acc[0][1], aa, bv.y);
            aa = pk2(av.y, av.y); fma2(acc[1][0], aa, bv.x); fma2(acc[1][1], aa, bv.y);
            aa = pk2(av.z, av.z); fma2(acc[2][0], aa, bv.x); fma2(acc[2][1], aa, bv.y);
            aa = pk2(av.w, av.w); fma2(acc[3][0], aa, bv.x); fma2(acc[3][1], aa, bv.y);
        }
        // master partial dots (threads r<96 of each slice; 2 (b,g) pairs each)
        float mp0 = 0.f, mp1 = 0.f;
        if (r < 96) {
            for (int kk = kbeg; kk < kbeg + KH / 4; kk++) {
                float a = As[kk * APAD + mb];
                mp0 += a * Bsm[kk * 8 + mg0];
                mp1 += a * Bsm[kk * 8 + mg0 + 1];
            }
        }
        __syncthreads();   // As readable done -> alias as red/res

        ulonglong2 *red = (ulonglong2 *)As;
        float *res = (float *)(red + 3 * 512);   // [32][64]
        if (kc) {
            #pragma unroll
            for (int a = 0; a < 4; a++) {
                ulonglong2 v; v.x = acc[a][0]; v.y = acc[a][1];
                red[(size_t)(kc - 1) * 512 + a * 128 + r] = v;
            }
        }
        if (r < 96) *(float2 *)&Msum[kc * 192 + mid0] = make_float2(mp0, mp1);
        __syncthreads();

        if (kc == 0) {
            #pragma unroll
            for (int a = 0; a < 4; a++) {
                float2 s0 = up2(acc[a][0]), s1 = up2(acc[a][1]);
                #pragma unroll
                for (int q = 0; q < 3; q++) {
                    ulonglong2 v = red[(size_t)q * 512 + a * 128 + r];
                    float2 o0 = up2(v.x), o1 = up2(v.y);
                    s0.x += o0.x; s0.y += o0.y; s1.x += o1.x; s1.y += o1.y;
                }
                float4 w;
                w.x = s0.x + xkp[a].x; w.y = s0.y + xkp[a].y;
                w.z = s1.x + xkp[a].z; w.w = s1.y + xkp[a].w;
                *(float4 *)&res[(ty * 4 + a) * 64 + tx * 4] = w;
            }
        }
        if (tid >= 128 && tid < 160) {
            int b = tid - 128;
            float pre[6];
            #pragma unroll
            for (int g = 0; g < 6; g++)
                pre[g] = Msum[b * 6 + g] + Msum[192 + b * 6 + g]
                       + Msum[384 + b * 6 + g] + Msum[576 + b * 6 + g] + xkm[g];
            float m = fmaxf(pre[0], fmaxf(pre[1], pre[2]));
            float e0 = __expf(pre[0] - m), e1 = __expf(pre[1] - m), e2 = __expf(pre[2] - m);
            float inv = 1.f / (e0 + e1 + e2);
            float f0 = e0 * inv, f1 = f0 + e1 * inv, f2 = f1 + e2 * inv;
            fms[b * 3 + 0] = f0; fms[b * 3 + 1] = f1; fms[b * 3 + 2] = f2;
            float mi = fmaxf(pre[3], fmaxf(pre[4], pre[5]));
            float q0 = __expf(pre[3] - mi), q1 = __expf(pre[4] - mi), q2 = __expf(pre[5] - mi);
            float iv = 1.f / (q0 + q1 + q2);
            float i2 = q2 * iv, i1 = i2 + q1 * iv, i0 = i1 + q0 * iv;
            ims[b * 3 + 0] = i0; ims[b * 3 + 1] = i1; ims[b * 3 + 2] = i2;
            if (gt == 0) g_dist[t * BB + b0 + b] = 1.f - (f0 + f1 + f2) * (1.f / 3.f);
        }
        __syncthreads();

        // block-local update (thread owns (b, i); c stays in register)
        {
            float fgv = sgm(res[ub * 64 + um]);
            float igv = sgm(res[ub * 64 + 16 + um]);
            float ogv = sgm(res[ub * 64 + 32 + um]);
            float civ = ftanh(res[ub * 64 + 48 + um]);
            float fm = fms[ub * 3 + ul], im = ims[ub * 3 + ul];
            float ov = fm * im;
            creg = creg * (ov * fgv + fm - ov) + civ * (ov * igv + im - ov);
            g_h[((size_t)t * BB + b0 + ub) * HH + ui] = ogv * ftanh(creg);
        }
        group_bar(bt);
    }
}

// ---------- theme ----------
__global__ __launch_bounds__(256) void theme_kernel(
    const float * __restrict__ Ws, const float * __restrict__ bs,
    const float * __restrict__ Wrs, const float * __restrict__ brs)
{
    int t = blockIdx.x, b0 = blockIdx.y * 8, tid = threadIdx.x;
    __shared__ float dis_s[8][CK], wm[8][HH], s1[8][HSS];
    if (tid < 8) calc_dis(t, b0 + tid, dis_s[tid]);
    __syncthreads();
    #pragma unroll
    for (int j = 0; j < 12; j++) {
        int e = tid + j * 256, b = e / HH, i = e % HH;
        float a = 0.f;
        #pragma unroll
        for (int k = 0; k < CK; k++) {
            int s = t - (CK - 1) + k;
            if (s >= 0) a += dis_s[b][k] * g_h[((size_t)s * BB + b0 + b) * HH + i];
        }
        wm[b][i] = a * (1.f / CK);
    }
    __syncthreads();
    #pragma unroll
    for (int j = 0; j < 2; j++) {
        int e = tid + j * 256, b = e / HSS, hs = e % HSS;
        float a = 0.f;
        for (int i = 0; i < HH; i++) a += wm[b][i] * Ws[i * HSS + hs];
        s1[b][hs] = fmaxf(a + bs[hs], 0.f);
    }
    __syncthreads();
    #pragma unroll
    for (int j = 0; j < 12; j++) {
        int e = tid + j * 256, b = e / HH, o = e % HH;
        float a = 0.f;
        #pragma unroll
        for (int hs = 0; hs < HSS; hs++) a += s1[b][hs] * Wrs[hs * HH + o];
        g_theme[((size_t)t * BB + b0 + b) * HH + o] = sgm(a + brs[o]);
    }
}

// ---------- conv ----------
#define CONV_FFMA(COMP)                                                     \
    {                                                                       \
        ulonglong2 b0v = *(const ulonglong2 *)&Bs[kk][tx * 4];              \
        ulonglong2 b1v = *(const ulonglong2 *)&Bs[kk][tx * 4 + 64];         \
        _Pragma("unroll")                                                   \
        for (int rr = 0; rr < 8; rr++) {                                    \
            float av = a4[rr].COMP;                                         \
            u64 aa = pk2(av, av);                                           \
            fma2(acc[rr][0], aa, b0v.x); fma2(acc[rr][1], aa, b0v.y);       \
            fma2(acc[rr][2], aa, b1v.x); fma2(acc[rr][3], aa, b1v.y);       \
        }                                                                   \
        kk++;                                                               \
    }

__global__ __launch_bounds__(256) void conv_kernel(const float * __restrict__ bc,
                                                   float * __restrict__ out)
{
    int t = blockIdx.x, o0 = blockIdx.y * 128, tid = threadIdx.x;
    int tx = tid & 15, ty = tid >> 4;
    __shared__ float dis_s[BB][CK];
    __shared__ __align__(16) float As[BB][36];
    __shared__ __align__(16) float Bs[32][128];
    if (tid < BB) calc_dis(t, tid, dis_s[tid]);
    __syncthreads();

    u64 acc[8][4];
    #pragma unroll
    for (int a = 0; a < 8; a++)
        #pragma unroll
        for (int c = 0; c < 4; c++) acc[a][c] = 0ull;

    const int NCH = CK * (HH / 32);
    float4 pa[4], pb[4];
    {
        int s = t - (CK - 1);
        #pragma unroll
        for (int l = 0; l < 4; l++) {
            int f = tid + l * 256;
            int ab = f >> 3, ai = (f & 7) * 4;
            pa[l].x = pa[l].y = pa[l].z = pa[l].w = 0.f;
            if (s >= 0) pa[l] = *(const float4 *)&g_h[((size_t)s * BB + ab) * HH + ai];
            int br_ = f >> 5, bo = (f & 31) * 4;
            pb[l] = *(const float4 *)&g_wct[(size_t)br_ * HH + o0 + bo];
        }
    }
    for (int ch = 0; ch < NCH; ch++) {
        int k = ch / 12;
        __syncthreads();
        #pragma unroll
        for (int l = 0; l < 4; l++) {
            int f = tid + l * 256;
            int ab = f >> 3, ai = (f & 7) * 4;
            float d = dis_s[ab][k];
            float4 v = pa[l];
            v.x *= d; v.y *= d; v.z *= d; v.w *= d;
            *(float4 *)&As[ab][ai] = v;
            int br_ = f >> 5, bo = (f & 31) * 4;
            *(float4 *)&Bs[br_][bo] = pb[l];
        }
        __syncthreads();
        if (ch + 1 < NCH) {
            int k2 = (ch + 1) / 12, i0 = ((ch + 1) % 12) * 32, s = t - (CK - 1) + k2;
            #pragma unroll
            for (int l = 0; l < 4; l++) {
                int f = tid + l * 256;
                int ab = f >> 3, ai = (f & 7) * 4;
                pa[l].x = pa[l].y = pa[l].z = pa[l].w = 0.f;
                if (s >= 0) pa[l] = *(const float4 *)&g_h[((size_t)s * BB + ab) * HH + i0 + ai];
                int br_ = f >> 5, bo = (f & 31) * 4;
                pb[l] = *(const float4 *)&g_wct[((size_t)k2 * HH + i0 + br_) * HH + o0 + bo];
            }
        }
        #pragma unroll
        for (int kq = 0; kq < 8; kq++) {
            float4 a4[8];
            #pragma unroll
            for (int rr = 0; rr < 8; rr++)
                a4[rr] = *(const float4 *)&As[ty * 8 + rr][kq * 4];
            int kk = kq * 4;
            CONV_FFMA(x) CONV_FFMA(y) CONV_FFMA(z) CONV_FFMA(w)
        }
    }
    #pragma unroll
    for (int rr = 0; rr < 8; rr++) {
        int b = ty * 8 + rr;
        #pragma unroll
        for (int c = 0; c < 4; c++) {
            float2 v = up2(acc[rr][c]);
            #pragma unroll
            for (int l = 0; l < 2; l++) {
                int o = o0 + (c >> 1) * 64 + tx * 4 + (c & 1) * 2 + l;
                float cv = (l ? v.y : v.x) + bc[o];
                out[((size_t)b * TT + t) * HH + o] =
                    g_theme[((size_t)t * BB + b) * HH + o] * cv +
                    g_h[((size_t)t * BB + b) * HH + o];
            }
        }
    }
}

extern "C" void kernel_launch(void* const* d_in, const int* in_sizes, int n_in,
                              void* d_out, int out_size) {
    const float *x   = (const float *)d_in[0];
    const float *Wk  = (const float *)d_in[2];
    const float *bk  = (const float *)d_in[3];
    const float *Wr  = (const float *)d_in[4];
    const float *br  = (const float *)d_in[5];
    const float *Ws  = (const float *)d_in[6];
    const float *bs  = (const float *)d_in[7];
    const float *Wrs = (const float *)d_in[8];
    const float *brs = (const float *)d_in[9];
    const float *Wc  = (const float *)d_in[10];
    const float *bc  = (const float *)d_in[11];
    float *out = (float *)d_out;

    const int smem_floats = KH * 64 + KH * 8 + KH * APAD + 4 * 192 + 96 + 96;
    const int smem_bytes = smem_floats * 4;   // 175,872 B
    cudaFuncSetAttribute(phase1_main,
                         cudaFuncAttributeMaxDynamicSharedMemorySize, smem_bytes);

    xk_kernel<<<dim3(512, 13), 256>>>(x, Wk, bk, Wr, br);
    wct_kernel<<<(CK * HH * HH + 255) / 256, 256>>>(Wc);
    phase1_main<<<NBLK, 512, smem_bytes>>>(Wr);
    theme_kernel<<<dim3(TT, 16), 256>>>(Ws, bs, Wrs, brs);
    conv_kernel<<<dim3(TT, 3), 256>>>(bc, out);
}